// round 1
// baseline (speedup 1.0000x reference)
#include <cuda_runtime.h>
#include <math.h>

// Problem shape (fixed by the dataset)
#define BB 16
#define CC 2
#define TT 2000
#define FF 257
#define NCHUNK 40
#define CL 50   // TT / NCHUNK

// Scratch for chunk carries / prefixes (no cudaMalloc allowed)
__device__ float g_carry[BB * NCHUNK * FF];

// Kernel 1: per-(b,f,chunk) local EMA scan starting from 0; store chunk aggregate.
__global__ void k1_partial(const float* __restrict__ in,
                           const float* __restrict__ alpha_p) {
    int f = threadIdx.x;
    if (f >= FF) return;
    int bc = blockIdx.x;            // b * NCHUNK + chunk
    int b = bc / NCHUNK;
    int chunk = bc % NCHUNK;

    float ap = alpha_p[f];
    float alpha = 1.0f / (1.0f + expf(-ap));
    float r = 1.0f - alpha;

    const float2* in0 = (const float2*)in + (size_t)(b * CC + 0) * TT * FF;
    int t0 = chunk * CL;
    float s = 0.0f;
#pragma unroll 5
    for (int t = t0; t < t0 + CL; ++t) {
        float2 x = in0[(size_t)t * FF + f];
        float d = x.x * x.x + x.y * x.y;
        s = fmaf(r, s, alpha * d);
    }
    g_carry[(size_t)bc * FF + f] = s;
}

// Kernel 2: per-(b,f) serial fold of chunk aggregates into exclusive prefixes.
__global__ void k2_combine(const float* __restrict__ s1,
                           const float* __restrict__ alpha_p) {
    int f = threadIdx.x;
    if (f >= FF) return;
    int b = blockIdx.x;

    float ap = alpha_p[f];
    float alpha = 1.0f / (1.0f + expf(-ap));
    float r = 1.0f - alpha;
    float rL = 1.0f;
#pragma unroll
    for (int i = 0; i < CL; ++i) rL *= r;   // r^CL

    float prefix = s1[b * FF + f];
    for (int c = 0; c < NCHUNK; ++c) {
        size_t idx = (size_t)(b * NCHUNK + c) * FF + f;
        float Bc = g_carry[idx];
        g_carry[idx] = prefix;              // exclusive prefix for chunk c
        prefix = fmaf(rL, prefix, Bc);
    }
}

// Kernel 3: re-scan each chunk with correct prefix; write smooth, res (both
// channels fused) and s_final.
__global__ void k3_final(const float* __restrict__ in,
                         const float* __restrict__ weights,
                         const float* __restrict__ bias,
                         const float* __restrict__ alpha_p,
                         float* __restrict__ res,
                         float* __restrict__ s_final,
                         float* __restrict__ smooth) {
    int f = threadIdx.x;
    if (f >= FF) return;
    int bc = blockIdx.x;
    int b = bc / NCHUNK;
    int chunk = bc % NCHUNK;

    float ap = alpha_p[f];
    float alpha = 1.0f / (1.0f + expf(-ap));
    float r = 1.0f - alpha;
    float w0 = weights[0 * FF + f], w1 = weights[1 * FF + f];
    float b0 = bias[0 * FF + f],    b1 = bias[1 * FF + f];

    const float2* in0 = (const float2*)in + (size_t)(b * CC + 0) * TT * FF;
    const float2* in1 = (const float2*)in + (size_t)(b * CC + 1) * TT * FF;
    float2* res0 = (float2*)res + (size_t)(b * CC + 0) * TT * FF;
    float2* res1 = (float2*)res + (size_t)(b * CC + 1) * TT * FF;
    float* sm_out = smooth + (size_t)b * TT * FF;

    float s = g_carry[(size_t)bc * FF + f];
    int t0 = chunk * CL;
#pragma unroll 2
    for (int t = t0; t < t0 + CL; ++t) {
        size_t idx = (size_t)t * FF + f;
        float2 x0 = in0[idx];
        float2 x1 = in1[idx];

        float d0 = x0.x * x0.x + x0.y * x0.y;
        s = fmaf(r, s, alpha * d0);
        float sm = sqrtf(s);
        sm_out[idx] = sm;

        float inv0 = w0 / (sm + 1e-8f);
        float m1 = sqrtf(x1.x * x1.x + x1.y * x1.y);
        float inv1 = w1 / (m1 + 1e-8f);

        res0[idx] = make_float2(fmaf(x0.x, inv0, b0), fmaf(x0.y, inv0, b0));
        res1[idx] = make_float2(fmaf(x1.x, inv1, b1), fmaf(x1.y, inv1, b1));
    }
    if (chunk == NCHUNK - 1) s_final[b * FF + f] = s;
}

extern "C" void kernel_launch(void* const* d_in, const int* in_sizes, int n_in,
                              void* d_out, int out_size) {
    // metadata order: input, s_1, weights, bias, alpha_param
    const float* in = (const float*)d_in[0];
    const float* s1 = (const float*)d_in[1];
    const float* w  = (const float*)d_in[2];
    const float* bi = (const float*)d_in[3];
    const float* ap = (const float*)d_in[4];

    float* out = (float*)d_out;
    float* res     = out;                                        // [B,C,T,F,2]
    float* s_final = out + (size_t)BB * CC * TT * FF * 2;        // [B,1,F,1]
    float* smooth  = s_final + (size_t)BB * FF;                  // [B,1,T,F,1]

    k1_partial<<<BB * NCHUNK, 288>>>(in, ap);
    k2_combine<<<BB, 288>>>(s1, ap);
    k3_final<<<BB * NCHUNK, 288>>>(in, w, bi, ap, res, s_final, smooth);
}